// round 4
// baseline (speedup 1.0000x reference)
#include <cuda_runtime.h>
#include <cstddef>

#define BB 16384
#define GG 128
#define SS 64
#define HH 10
#define PHH 100

// 8MB scratch for gene_layer, stored TRANSPOSED: glT[g][b]
__device__ float g_glT[GG * BB];

// packed fp32x2 FMA (Blackwell; inline PTX only)
__device__ __forceinline__ unsigned long long f2fma(unsigned long long a,
                                                    unsigned long long b,
                                                    unsigned long long c) {
    unsigned long long d;
    asm("fma.rn.f32x2 %0, %1, %2, %3;" : "=l"(d) : "l"(a), "l"(b), "l"(c));
    return d;
}
__device__ __forceinline__ float f2lo(unsigned long long a) {
    return __uint_as_float((unsigned)a);
}
__device__ __forceinline__ float f2hi(unsigned long long a) {
    return __uint_as_float((unsigned)(a >> 32));
}
__device__ __forceinline__ unsigned long long f2dup(float v) {
    unsigned long long d;
    asm("mov.b64 %0, {%1, %1};" : "=l"(d) : "f"(v));
    return d;
}

extern __shared__ unsigned char dynsmem[];

// ---------------------------------------------------------------------------
// Kernel A: gene_layer[b,g] = W2 . relu(x[b,g,:] @ W1[g] + b1) + b2
// Block = (gene, 256-row tile), 64 threads, R=4 rows/thread.
// W-broadcast LDS amortized 4x: crossbar/32rows = 64(STS)+64(x)+160(W) = 288.
// ---------------------------------------------------------------------------
#define AR 256      // rows per block
#define ATH 64      // threads
#define XPAD 68     // floats per smem row (64 + 4): conflict-free LDS.128 phases

// floats: xs[AR][XPAD] + wt[HH][SS] + sb1[16] + sW2[16] + sb2[4]
#define A_SMEM_FLOATS (AR * XPAD + HH * SS + 36)
#define A_SMEM_BYTES (A_SMEM_FLOATS * 4)

__global__ void __launch_bounds__(ATH)
kernelA(const float* __restrict__ x, const float* __restrict__ W1,
        const float* __restrict__ b1, const float* __restrict__ W2,
        const float* __restrict__ b2) {
    float* xs  = (float*)dynsmem;        // [AR][XPAD]
    float* wt  = xs + AR * XPAD;         // [HH][SS]  wt[h][s]
    float* sb1 = wt + HH * SS;           // [16]
    float* sW2 = sb1 + 16;               // [16]
    float* sb2 = sW2 + 16;               // [1]

    const int tid = threadIdx.x;
    const int g = blockIdx.x;
    const int b0 = blockIdx.y * AR;

    // stage W1[g] transposed (tiny)
    {
        const float* W1g = W1 + (size_t)g * (SS * HH);
        for (int i = tid; i < SS * HH; i += ATH) {
            int s = i / HH, h = i - s * HH;
            wt[h * SS + s] = W1g[i];
        }
        if (tid < HH) {
            sb1[tid] = b1[g * HH + tid];
            sW2[tid] = W2[g * HH + tid];
        }
        if (tid == 0) sb2[0] = b2[g];
    }

    // stage x tile coalesced: xs[r][0..63] = x[b0+r, g, :]
#pragma unroll 8
    for (int i = tid; i < AR * 16; i += ATH) {
        int r = i >> 4, q = i & 15;
        float4 v = *(const float4*)(x + (((size_t)(b0 + r)) * GG + g) * SS + 4 * q);
        *(float4*)(xs + r * XPAD + 4 * q) = v;
    }
    __syncthreads();

    // compute: rows tid, tid+64, tid+128, tid+192; q outer, h inner
    unsigned long long a0[HH], a1[HH], a2[HH], a3[HH];
#pragma unroll
    for (int h = 0; h < HH; h++) { a0[h] = 0ull; a1[h] = 0ull; a2[h] = 0ull; a3[h] = 0ull; }

#pragma unroll 2
    for (int q = 0; q < 16; q++) {
        ulonglong2 xa = *(const ulonglong2*)(xs + (tid)       * XPAD + 4 * q);
        ulonglong2 xb = *(const ulonglong2*)(xs + (tid + 64)  * XPAD + 4 * q);
        ulonglong2 xc = *(const ulonglong2*)(xs + (tid + 128) * XPAD + 4 * q);
        ulonglong2 xd = *(const ulonglong2*)(xs + (tid + 192) * XPAD + 4 * q);
#pragma unroll
        for (int h = 0; h < HH; h++) {
            ulonglong2 w = *(const ulonglong2*)(wt + h * SS + 4 * q);  // broadcast
            a0[h] = f2fma(xa.x, w.x, a0[h]);
            a1[h] = f2fma(xb.x, w.x, a1[h]);
            a2[h] = f2fma(xc.x, w.x, a2[h]);
            a3[h] = f2fma(xd.x, w.x, a3[h]);
            a0[h] = f2fma(xa.y, w.y, a0[h]);
            a1[h] = f2fma(xb.y, w.y, a1[h]);
            a2[h] = f2fma(xc.y, w.y, a2[h]);
            a3[h] = f2fma(xd.y, w.y, a3[h]);
        }
    }

    // epilogue: relu + H->1 projection, coalesced store
    float o0 = sb2[0], o1 = sb2[0], o2 = sb2[0], o3 = sb2[0];
#pragma unroll
    for (int h = 0; h < HH; h++) {
        float v0 = f2lo(a0[h]) + f2hi(a0[h]) + sb1[h];
        float v1 = f2lo(a1[h]) + f2hi(a1[h]) + sb1[h];
        float v2 = f2lo(a2[h]) + f2hi(a2[h]) + sb1[h];
        float v3 = f2lo(a3[h]) + f2hi(a3[h]) + sb1[h];
        o0 = fmaf(fmaxf(v0, 0.f), sW2[h], o0);
        o1 = fmaf(fmaxf(v1, 0.f), sW2[h], o1);
        o2 = fmaf(fmaxf(v2, 0.f), sW2[h], o2);
        o3 = fmaf(fmaxf(v3, 0.f), sW2[h], o3);
    }
    float* glrow = g_glT + (size_t)g * BB + b0;
    glrow[tid]       = o0;
    glrow[tid + 64]  = o1;
    glrow[tid + 128] = o2;
    glrow[tid + 192] = o3;
}

// ---------------------------------------------------------------------------
// Kernel B: out[b] = relu(gl[b,:] @ Wp1 + bp1) @ Wp2 + bp2
// 256 blocks x 256 threads. Thread = (rowslot 0..31 -> rows r, r+32) x
// (jsub 0..7 -> 16 j each, PH padded to 128). f32x2 over j-pairs, R=2 rows.
// ---------------------------------------------------------------------------
#define B_THREADS 256
#define B_ROWSB 64
#define PHP 128
#define B_SMEM_FLOATS (GG * B_ROWSB + GG * PHP + PHP + PHP + 8 * B_ROWSB)
#define B_SMEM_BYTES (B_SMEM_FLOATS * 4)

__global__ void __launch_bounds__(B_THREADS)
kernelB(const float* __restrict__ Wp1, const float* __restrict__ bp1,
        const float* __restrict__ Wp2, const float* __restrict__ bp2,
        float* __restrict__ out) {
    float* gls  = (float*)dynsmem;            // [G][64] (g-major)
    float* sWp1 = gls + GG * B_ROWSB;         // [G][128] zero-padded
    float* sbp1 = sWp1 + GG * PHP;            // [128]
    float* sWp2 = sbp1 + PHP;                 // [128]
    float* op   = sWp2 + PHP;                 // [8][64] partials

    const int tid = threadIdx.x;
    const int b0 = blockIdx.x * B_ROWSB;

    // stage gene_layer tile (vectorized, coalesced from transposed scratch)
#pragma unroll 4
    for (int i = tid; i < GG * (B_ROWSB / 4); i += B_THREADS) {
        int k = i & 15, g = i >> 4;   // 16 float4 per gene row
        *(float4*)(gls + g * B_ROWSB + 4 * k) =
            *(const float4*)(g_glT + (size_t)g * BB + b0 + 4 * k);
    }
#pragma unroll 4
    for (int i = tid; i < GG * PHP; i += B_THREADS) {
        int g = i >> 7, j = i & (PHP - 1);
        sWp1[i] = (j < PHH) ? Wp1[g * PHH + j] : 0.f;
    }
    if (tid < PHP) {
        sbp1[tid] = (tid < PHH) ? bp1[tid] : 0.f;
        sWp2[tid] = (tid < PHH) ? Wp2[tid] : 0.f;
    }
    __syncthreads();

    const int row  = tid & 31;        // rows: row, row+32
    const int jsub = tid >> 5;        // warp-uniform: 8 subsets x 16 j
    const int jb   = jsub * 16;

    unsigned long long acc0[8], acc1[8];
#pragma unroll
    for (int c = 0; c < 8; c++) { acc0[c] = 0ull; acc1[c] = 0ull; }

#pragma unroll 4
    for (int g = 0; g < GG; g++) {
        unsigned long long x0 = f2dup(gls[g * B_ROWSB + row]);
        unsigned long long x1 = f2dup(gls[g * B_ROWSB + row + 32]);
        const ulonglong2* wp = (const ulonglong2*)(sWp1 + g * PHP + jb);
        ulonglong2 w0 = wp[0];
        ulonglong2 w1 = wp[1];
        acc0[0] = f2fma(x0, w0.x, acc0[0]);  acc1[0] = f2fma(x1, w0.x, acc1[0]);
        acc0[1] = f2fma(x0, w0.y, acc0[1]);  acc1[1] = f2fma(x1, w0.y, acc1[1]);
        acc0[2] = f2fma(x0, w1.x, acc0[2]);  acc1[2] = f2fma(x1, w1.x, acc1[2]);
        acc0[3] = f2fma(x0, w1.y, acc0[3]);  acc1[3] = f2fma(x1, w1.y, acc1[3]);
        ulonglong2 w2 = wp[2];
        ulonglong2 w3 = wp[3];
        acc0[4] = f2fma(x0, w2.x, acc0[4]);  acc1[4] = f2fma(x1, w2.x, acc1[4]);
        acc0[5] = f2fma(x0, w2.y, acc0[5]);  acc1[5] = f2fma(x1, w2.y, acc1[5]);
        acc0[6] = f2fma(x0, w3.x, acc0[6]);  acc1[6] = f2fma(x1, w3.x, acc1[6]);
        acc0[7] = f2fma(x0, w3.y, acc0[7]);  acc1[7] = f2fma(x1, w3.y, acc1[7]);
    }

    float o0 = 0.f, o1 = 0.f;
#pragma unroll
    for (int c = 0; c < 8; c++) {
        int j0 = jb + 2 * c, j1 = j0 + 1;
        float p00 = fmaxf(f2lo(acc0[c]) + sbp1[j0], 0.f);
        float p01 = fmaxf(f2hi(acc0[c]) + sbp1[j1], 0.f);
        float p10 = fmaxf(f2lo(acc1[c]) + sbp1[j0], 0.f);
        float p11 = fmaxf(f2hi(acc1[c]) + sbp1[j1], 0.f);
        o0 = fmaf(p00, sWp2[j0], o0);
        o0 = fmaf(p01, sWp2[j1], o0);
        o1 = fmaf(p10, sWp2[j0], o1);
        o1 = fmaf(p11, sWp2[j1], o1);
    }
    op[jsub * B_ROWSB + row]      = o0;
    op[jsub * B_ROWSB + row + 32] = o1;
    __syncthreads();

    if (tid < B_ROWSB) {
        float v = bp2[0];
#pragma unroll
        for (int c = 0; c < 8; c++) v += op[c * B_ROWSB + tid];
        out[b0 + tid] = v;
    }
}

// ---------------------------------------------------------------------------
extern "C" void kernel_launch(void* const* d_in, const int* in_sizes, int n_in,
                              void* d_out, int out_size) {
    const float* x   = (const float*)d_in[0];
    const float* W1  = (const float*)d_in[1];
    const float* b1  = (const float*)d_in[2];
    const float* W2  = (const float*)d_in[3];
    const float* b2  = (const float*)d_in[4];
    const float* Wp1 = (const float*)d_in[5];
    const float* bp1 = (const float*)d_in[6];
    const float* Wp2 = (const float*)d_in[7];
    const float* bp2 = (const float*)d_in[8];
    float* out = (float*)d_out;

    cudaFuncSetAttribute(kernelA, cudaFuncAttributeMaxDynamicSharedMemorySize,
                         A_SMEM_BYTES);
    cudaFuncSetAttribute(kernelB, cudaFuncAttributeMaxDynamicSharedMemorySize,
                         B_SMEM_BYTES);

    dim3 gridA(GG, BB / AR);   // concurrent wave covers contiguous x slab
    kernelA<<<gridA, ATH, A_SMEM_BYTES>>>(x, W1, b1, W2, b2);

    dim3 gridB(BB / B_ROWSB);
    kernelB<<<gridB, B_THREADS, B_SMEM_BYTES>>>(Wp1, bp1, Wp2, bp2, out);
}